// round 4
// baseline (speedup 1.0000x reference)
#include <cuda_runtime.h>
#include <math.h>

// Input order (metadata):
// 0 pred_Rot1  [BS,3]        f32
// 1 pred_Rot2  [BS,3]        f32
// 2 pred_Recon [BS,N_PTS,3]  f32
// 3 pred_Tran  [BS,3]        f32
// 4 pred_Size  [BS,3]        f32
// 5 gt_Rotation[BS,3,3]      f32
// 6 gt_Recon   [BS,N_PTS,3]  f32
// 7 gt_Tran    [BS,3]        f32
// 8 gt_Size    [BS,3]        f32
// 9 sym        [BS,6]        i32
// out: 5 f32  [8*rot1, 8*rot2, 8*recon, 8*tran, 8*size]

#define BASE 12
#define RBLK_MAX 1184
#define RTHR 256
#define NWARP (RTHR / 32)

__device__ float g_partials[RBLK_MAX];
__device__ unsigned int g_ticket;   // zero-init at load; finisher resets

// Compile-time cos/sin tables for theta_k = k * 2pi/12
__constant__ float c_cos[BASE] = {
    1.0f,  0.8660254037844387f,  0.5f,  0.0f, -0.5f, -0.8660254037844387f,
   -1.0f, -0.8660254037844387f, -0.5f,  0.0f,  0.5f,  0.8660254037844387f};
__constant__ float c_sin[BASE] = {
    0.0f,  0.5f,  0.8660254037844387f,  1.0f,  0.8660254037844387f,  0.5f,
    0.0f, -0.5f, -0.8660254037844387f, -1.0f, -0.8660254037844387f, -0.5f};

__device__ __forceinline__ float warp_sum(float v) {
    #pragma unroll
    for (int o = 16; o > 0; o >>= 1) v += __shfl_down_sync(0xffffffffu, v, o);
    return v;
}

// ---------------------------------------------------------------------------
// Single fused kernel: streaming L1 reduction; the last block to finish
// becomes the finisher and computes all five losses.
// ---------------------------------------------------------------------------
__global__ void __launch_bounds__(RTHR, 4)
fsnet_loss_kernel(const float* __restrict__ pf, const float* __restrict__ gf,
                  const float* __restrict__ pR1, const float* __restrict__ pR2,
                  const float* __restrict__ pT,  const float* __restrict__ pS,
                  const float* __restrict__ gR,  const float* __restrict__ gT,
                  const float* __restrict__ gS,  const int* __restrict__ sym,
                  float* __restrict__ out,
                  int n4, int ntail, int nblocks, int bs, int n_recon_elems) {
    const int t = threadIdx.x;
    const int lane = t & 31;
    const int wid = t >> 5;
    __shared__ float shw[NWARP];
    __shared__ bool is_last;

    // ---- phase 1: streaming L1 partial ----
    const float4* __restrict__ p = (const float4*)pf;
    const float4* __restrict__ g = (const float4*)gf;
    float acc = 0.0f;
    {
        int idx = blockIdx.x * RTHR + t;
        const int stride = nblocks * RTHR;
        #pragma unroll 4
        for (int i = idx; i < n4; i += stride) {
            float4 a = __ldg(&p[i]);
            float4 b = __ldg(&g[i]);
            acc += fabsf(a.x - b.x) + fabsf(a.y - b.y)
                 + fabsf(a.z - b.z) + fabsf(a.w - b.w);
        }
        if (blockIdx.x == 0 && t < ntail) {
            int base = n4 * 4 + t;
            acc += fabsf(pf[base] - gf[base]);
        }
    }
    acc = warp_sum(acc);
    if (lane == 0) shw[wid] = acc;
    __syncthreads();
    if (t == 0) {
        float bsum = 0.0f;
        #pragma unroll
        for (int w = 0; w < NWARP; w++) bsum += shw[w];
        g_partials[blockIdx.x] = bsum;
        __threadfence();
        unsigned int prev = atomicAdd(&g_ticket, 1u);
        is_last = (prev == (unsigned int)(nblocks - 1));
    }
    __syncthreads();
    if (!is_last) return;

    // ---- phase 2: finisher block ----
    __threadfence();   // acquire: see all partials

    float rsum = 0.0f;
    for (int i = t; i < nblocks; i += RTHR) rsum += g_partials[i];

    // small per-batch losses: thread t handles batch rows t, t+RTHR, ...
    float rot1_b = 0.0f, rot2num_b = 0.0f, mask_b = 0.0f;
    float tran_b = 0.0f, size_b = 0.0f;
    for (int b = t; b < bs; b += RTHR) {
        const float* R = gR + b * 9;
        float c0x = R[0], c0y = R[3], c0z = R[6];   // column 0
        float c1x = R[1], c1y = R[4], c1z = R[7];   // column 1
        float c2x = R[2], c2y = R[5], c2z = R[8];   // column 2

        float p0 = pR1[b * 3 + 0], p1 = pR1[b * 3 + 1], p2 = pR1[b * 3 + 2];
        float l1a = (fabsf(p0 - c1x) + fabsf(p1 - c1y) + fabsf(p2 - c1z)) * (1.0f / 3.0f);
        float l1b = (fabsf(p0 + c1x) + fabsf(p1 + c1y) + fabsf(p2 + c1z)) * (1.0f / 3.0f);
        rot1_b += (sym[b * 6 + 2] == 1) ? fminf(l1a, l1b) : l1a;

        float q0 = pR2[b * 3 + 0], q1 = pR2[b * 3 + 1], q2 = pR2[b * 3 + 2];
        float l2min = 3.4e38f;
        #pragma unroll
        for (int k = 0; k < BASE; k++) {
            float c = c_cos[k], s = c_sin[k];
            float vx = fmaf(c, c0x, -s * c2x);
            float vy = fmaf(c, c0y, -s * c2y);
            float vz = fmaf(c, c0z, -s * c2z);
            float l = (fabsf(q0 - vx) + fabsf(q1 - vy) + fabsf(q2 - vz)) * (1.0f / 3.0f);
            l2min = fminf(l2min, l);
        }
        float m = (sym[b * 6 + 0] == 0) ? 1.0f : 0.0f;
        mask_b += m;
        rot2num_b += l2min * m;

        tran_b += fabsf(pT[b * 3 + 0] - gT[b * 3 + 0])
                + fabsf(pT[b * 3 + 1] - gT[b * 3 + 1])
                + fabsf(pT[b * 3 + 2] - gT[b * 3 + 2]);
        size_b += fabsf(pS[b * 3 + 0] - gS[b * 3 + 0])
                + fabsf(pS[b * 3 + 1] - gS[b * 3 + 1])
                + fabsf(pS[b * 3 + 2] - gS[b * 3 + 2]);
    }

    // ---- six reductions via warp shuffles + one shared pass ----
    __shared__ float sh6[NWARP][6];
    float vals[6] = {rsum, rot1_b, rot2num_b, mask_b, tran_b, size_b};
    #pragma unroll
    for (int v = 0; v < 6; v++) vals[v] = warp_sum(vals[v]);
    if (lane == 0) {
        #pragma unroll
        for (int v = 0; v < 6; v++) sh6[wid][v] = vals[v];
    }
    __syncthreads();

    if (t == 0) {
        float sums[6];
        #pragma unroll
        for (int v = 0; v < 6; v++) {
            float s = 0.0f;
            #pragma unroll
            for (int w = 0; w < NWARP; w++) s += sh6[w][v];
            sums[v] = s;
        }
        float recon = sums[0] / (float)n_recon_elems;
        float rot1  = sums[1] / (float)bs;
        float rot2  = (sums[3] > 0.0f) ? sums[2] / fmaxf(sums[3], 1.0f) : 0.0f;
        float tran  = sums[4] / (float)(bs * 3);
        float size  = sums[5] / (float)(bs * 3);
        out[0] = 8.0f * rot1;
        out[1] = 8.0f * rot2;
        out[2] = 8.0f * recon;
        out[3] = 8.0f * tran;
        out[4] = 8.0f * size;
        g_ticket = 0u;   // reset for next graph replay
    }
}

extern "C" void kernel_launch(void* const* d_in, const int* in_sizes, int n_in,
                              void* d_out, int out_size) {
    const float* pred_Rot1  = (const float*)d_in[0];
    const float* pred_Rot2  = (const float*)d_in[1];
    const float* pred_Recon = (const float*)d_in[2];
    const float* pred_Tran  = (const float*)d_in[3];
    const float* pred_Size  = (const float*)d_in[4];
    const float* gt_Rot     = (const float*)d_in[5];
    const float* gt_Recon   = (const float*)d_in[6];
    const float* gt_Tran    = (const float*)d_in[7];
    const float* gt_Size    = (const float*)d_in[8];
    const int*   sym        = (const int*)d_in[9];
    float* out = (float*)d_out;

    const int n_recon = in_sizes[2];
    const int bs      = in_sizes[0] / 3;
    const int n4      = n_recon / 4;
    const int ntail   = n_recon - n4 * 4;

    int nblocks = (n4 + RTHR - 1) / RTHR;
    if (nblocks > RBLK_MAX) nblocks = RBLK_MAX;
    if (nblocks < 1) nblocks = 1;

    fsnet_loss_kernel<<<nblocks, RTHR>>>(pred_Recon, gt_Recon,
                                         pred_Rot1, pred_Rot2, pred_Tran, pred_Size,
                                         gt_Rot, gt_Tran, gt_Size, sym, out,
                                         n4, ntail, nblocks, bs, n_recon);
}

// round 5
// speedup vs baseline: 1.3099x; 1.3099x over previous
#include <cuda_runtime.h>
#include <math.h>

// Input order (metadata):
// 0 pred_Rot1  [BS,3]  1 pred_Rot2 [BS,3]  2 pred_Recon [BS,N_PTS,3]
// 3 pred_Tran  [BS,3]  4 pred_Size [BS,3]  5 gt_Rotation [BS,3,3]
// 6 gt_Recon [BS,N_PTS,3]  7 gt_Tran [BS,3]  8 gt_Size [BS,3]  9 sym [BS,6] i32
// out: 5 f32  [8*rot1, 8*rot2, 8*recon, 8*tran, 8*size]

#define BASE 12
#define RBLK_MAX 1184          // 148 SMs * 8 blocks -> exactly one wave
#define RTHR 256
#define NWARP (RTHR / 32)

__device__ float g_partials[RBLK_MAX];
__device__ unsigned int g_ticket;   // zero-init at load; finisher resets

__constant__ float c_cos[BASE] = {
    1.0f,  0.8660254037844387f,  0.5f,  0.0f, -0.5f, -0.8660254037844387f,
   -1.0f, -0.8660254037844387f, -0.5f,  0.0f,  0.5f,  0.8660254037844387f};
__constant__ float c_sin[BASE] = {
    0.0f,  0.5f,  0.8660254037844387f,  1.0f,  0.8660254037844387f,  0.5f,
    0.0f, -0.5f, -0.8660254037844387f, -1.0f, -0.8660254037844387f, -0.5f};

__device__ __forceinline__ float warp_sum(float v) {
    #pragma unroll
    for (int o = 16; o > 0; o >>= 1) v += __shfl_down_sync(0xffffffffu, v, o);
    return v;
}

// ---------------------------------------------------------------------------
// Fused kernel. __launch_bounds__(256, 8) caps regs at 32 so the streaming
// phase runs at FULL occupancy (the R4 regression was 64 regs -> 50% occ).
// The finisher phase may spill to local; it runs in exactly one block.
// ---------------------------------------------------------------------------
__global__ void __launch_bounds__(RTHR, 8)
fsnet_loss_kernel(const float* __restrict__ pf, const float* __restrict__ gf,
                  const float* __restrict__ pR1, const float* __restrict__ pR2,
                  const float* __restrict__ pT,  const float* __restrict__ pS,
                  const float* __restrict__ gR,  const float* __restrict__ gT,
                  const float* __restrict__ gS,  const int* __restrict__ sym,
                  float* __restrict__ out,
                  int n4, int ntail, int nblocks, int bs, int n_recon_elems) {
    const int t = threadIdx.x;
    const int lane = t & 31;
    const int wid = t >> 5;
    __shared__ float shw[NWARP];
    __shared__ bool is_last;

    // ---- phase 1: streaming L1 partial (lean: keep within 32 regs) ----
    const float4* __restrict__ p = (const float4*)pf;
    const float4* __restrict__ g = (const float4*)gf;
    float acc0 = 0.0f, acc1 = 0.0f;
    {
        int idx = blockIdx.x * RTHR + t;
        const int stride = nblocks * RTHR;
        int i = idx;
        // main: two independent accumulators, 2 iters in flight
        for (; i + stride < n4; i += 2 * stride) {
            float4 a0 = __ldg(&p[i]);
            float4 b0 = __ldg(&g[i]);
            float4 a1 = __ldg(&p[i + stride]);
            float4 b1 = __ldg(&g[i + stride]);
            acc0 += fabsf(a0.x - b0.x) + fabsf(a0.y - b0.y)
                  + fabsf(a0.z - b0.z) + fabsf(a0.w - b0.w);
            acc1 += fabsf(a1.x - b1.x) + fabsf(a1.y - b1.y)
                  + fabsf(a1.z - b1.z) + fabsf(a1.w - b1.w);
        }
        if (i < n4) {
            float4 a = __ldg(&p[i]);
            float4 b = __ldg(&g[i]);
            acc0 += fabsf(a.x - b.x) + fabsf(a.y - b.y)
                  + fabsf(a.z - b.z) + fabsf(a.w - b.w);
        }
        if (blockIdx.x == 0 && t < ntail) {
            int base = n4 * 4 + t;
            acc0 += fabsf(pf[base] - gf[base]);
        }
    }
    float acc = warp_sum(acc0 + acc1);
    if (lane == 0) shw[wid] = acc;
    __syncthreads();
    if (t == 0) {
        float bsum = 0.0f;
        #pragma unroll
        for (int w = 0; w < NWARP; w++) bsum += shw[w];
        g_partials[blockIdx.x] = bsum;
        __threadfence();
        unsigned int prev = atomicAdd(&g_ticket, 1u);
        is_last = (prev == (unsigned int)(nblocks - 1));
    }
    __syncthreads();
    if (!is_last) return;

    // ---- phase 2: finisher (one block; spills OK) ----
    __threadfence();

    float rsum = 0.0f;
    for (int i = t; i < nblocks; i += RTHR) rsum += g_partials[i];

    float rot1_b = 0.0f, rot2num_b = 0.0f, mask_b = 0.0f;
    float tran_b = 0.0f, size_b = 0.0f;
    for (int b = t; b < bs; b += RTHR) {
        const float* R = gR + b * 9;
        float c0x = R[0], c0y = R[3], c0z = R[6];
        float c1x = R[1], c1y = R[4], c1z = R[7];
        float c2x = R[2], c2y = R[5], c2z = R[8];

        float p0 = pR1[b * 3 + 0], p1 = pR1[b * 3 + 1], p2 = pR1[b * 3 + 2];
        float l1a = (fabsf(p0 - c1x) + fabsf(p1 - c1y) + fabsf(p2 - c1z)) * (1.0f / 3.0f);
        float l1b = (fabsf(p0 + c1x) + fabsf(p1 + c1y) + fabsf(p2 + c1z)) * (1.0f / 3.0f);
        rot1_b += (sym[b * 6 + 2] == 1) ? fminf(l1a, l1b) : l1a;

        float q0 = pR2[b * 3 + 0], q1 = pR2[b * 3 + 1], q2 = pR2[b * 3 + 2];
        float l2min = 3.4e38f;
        #pragma unroll
        for (int k = 0; k < BASE; k++) {
            float c = c_cos[k], s = c_sin[k];
            float vx = fmaf(c, c0x, -s * c2x);
            float vy = fmaf(c, c0y, -s * c2y);
            float vz = fmaf(c, c0z, -s * c2z);
            float l = (fabsf(q0 - vx) + fabsf(q1 - vy) + fabsf(q2 - vz)) * (1.0f / 3.0f);
            l2min = fminf(l2min, l);
        }
        float m = (sym[b * 6 + 0] == 0) ? 1.0f : 0.0f;
        mask_b += m;
        rot2num_b += l2min * m;

        tran_b += fabsf(pT[b * 3 + 0] - gT[b * 3 + 0])
                + fabsf(pT[b * 3 + 1] - gT[b * 3 + 1])
                + fabsf(pT[b * 3 + 2] - gT[b * 3 + 2]);
        size_b += fabsf(pS[b * 3 + 0] - gS[b * 3 + 0])
                + fabsf(pS[b * 3 + 1] - gS[b * 3 + 1])
                + fabsf(pS[b * 3 + 2] - gS[b * 3 + 2]);
    }

    __shared__ float sh6[NWARP][6];
    float vals[6] = {rsum, rot1_b, rot2num_b, mask_b, tran_b, size_b};
    #pragma unroll
    for (int v = 0; v < 6; v++) vals[v] = warp_sum(vals[v]);
    if (lane == 0) {
        #pragma unroll
        for (int v = 0; v < 6; v++) sh6[wid][v] = vals[v];
    }
    __syncthreads();

    if (t == 0) {
        float sums[6];
        #pragma unroll
        for (int v = 0; v < 6; v++) {
            float s = 0.0f;
            #pragma unroll
            for (int w = 0; w < NWARP; w++) s += sh6[w][v];
            sums[v] = s;
        }
        float recon = sums[0] / (float)n_recon_elems;
        float rot1  = sums[1] / (float)bs;
        float rot2  = (sums[3] > 0.0f) ? sums[2] / fmaxf(sums[3], 1.0f) : 0.0f;
        float tran  = sums[4] / (float)(bs * 3);
        float size  = sums[5] / (float)(bs * 3);
        out[0] = 8.0f * rot1;
        out[1] = 8.0f * rot2;
        out[2] = 8.0f * recon;
        out[3] = 8.0f * tran;
        out[4] = 8.0f * size;
        g_ticket = 0u;   // reset for next graph replay
    }
}

extern "C" void kernel_launch(void* const* d_in, const int* in_sizes, int n_in,
                              void* d_out, int out_size) {
    const float* pred_Rot1  = (const float*)d_in[0];
    const float* pred_Rot2  = (const float*)d_in[1];
    const float* pred_Recon = (const float*)d_in[2];
    const float* pred_Tran  = (const float*)d_in[3];
    const float* pred_Size  = (const float*)d_in[4];
    const float* gt_Rot     = (const float*)d_in[5];
    const float* gt_Recon   = (const float*)d_in[6];
    const float* gt_Tran    = (const float*)d_in[7];
    const float* gt_Size    = (const float*)d_in[8];
    const int*   sym        = (const int*)d_in[9];
    float* out = (float*)d_out;

    const int n_recon = in_sizes[2];
    const int bs      = in_sizes[0] / 3;
    const int n4      = n_recon / 4;
    const int ntail   = n_recon - n4 * 4;

    int nblocks = (n4 + RTHR - 1) / RTHR;
    if (nblocks > RBLK_MAX) nblocks = RBLK_MAX;
    if (nblocks < 1) nblocks = 1;

    fsnet_loss_kernel<<<nblocks, RTHR>>>(pred_Recon, gt_Recon,
                                         pred_Rot1, pred_Rot2, pred_Tran, pred_Size,
                                         gt_Rot, gt_Tran, gt_Size, sym, out,
                                         n4, ntail, nblocks, bs, n_recon);
}